// round 7
// baseline (speedup 1.0000x reference)
#include <cuda_runtime.h>
#include <stdint.h>

// Embedding gather, fully async-engine version.
// out[j*64..] = pages[idx[j]*64..]  (row = 256 B), idx int32.
//
// R2-R5 showed the LDG/STG path is pinned at ~11us regardless of ILP/occ:
// the per-SM L1tex wavefront pipe (4 lines per gather LDG.128 + 4 per
// STG.128, amplified by cross-CTA queue spread) is the real bound and the
// roofline %s under-report it. This version moves ALL data through the
// async bulk-copy engine (UBLKCP), which bypasses L1tex:
//   - per-row 256B cp.async.bulk global->smem (mbarrier complete_tx)
//   - per-stage single 16KB cp.async.bulk smem->global (bulk_group)
// Pipelined over 4 smem stages, producer warp + storer thread.

#define N_WORDS        1000000
#define ROW_BYTES      256
#define ROWS_PER_STAGE 64
#define STAGE_BYTES    (ROWS_PER_STAGE * ROW_BYTES)   // 16384
#define STAGES         4
#define ROWS_PER_CTA   256                            // = 4 stages, no wrap reuse needed beyond ring
#define THREADS        64                             // warp0 producer, warp1 storer
#define SMEM_BUF_OFF   1024
#define SMEM_TOTAL     (SMEM_BUF_OFF + STAGES * STAGE_BYTES)   // 66560

__device__ __forceinline__ uint32_t smem_u32(const void* p) {
    uint32_t a;
    asm("{ .reg .u64 t; cvta.to.shared.u64 t, %1; cvt.u32.u64 %0, t; }"
        : "=r"(a) : "l"(p));
    return a;
}

__device__ __forceinline__ void mbar_init(uint32_t mbar, uint32_t count) {
    asm volatile("mbarrier.init.shared.b64 [%0], %1;" :: "r"(mbar), "r"(count) : "memory");
}

__device__ __forceinline__ void mbar_expect_tx(uint32_t mbar, uint32_t bytes) {
    asm volatile("mbarrier.arrive.expect_tx.shared.b64 _, [%0], %1;"
                 :: "r"(mbar), "r"(bytes) : "memory");
}

__device__ __forceinline__ void mbar_arrive(uint32_t mbar) {
    asm volatile("mbarrier.arrive.shared.b64 _, [%0];" :: "r"(mbar) : "memory");
}

__device__ __forceinline__ void mbar_wait(uint32_t mbar, uint32_t parity) {
    asm volatile(
        "{\n\t"
        ".reg .pred P;\n\t"
        "WAIT_%=:\n\t"
        "mbarrier.try_wait.parity.acquire.cta.shared::cta.b64 P, [%0], %1, 0x989680;\n\t"
        "@P bra.uni DONE_%=;\n\t"
        "bra.uni WAIT_%=;\n\t"
        "DONE_%=:\n\t"
        "}"
        :: "r"(mbar), "r"(parity) : "memory");
}

__device__ __forceinline__ void bulk_g2s(uint32_t smem_dst, const void* gsrc,
                                         uint32_t bytes, uint32_t mbar) {
    asm volatile(
        "cp.async.bulk.shared::cluster.global.mbarrier::complete_tx::bytes "
        "[%0], [%1], %2, [%3];"
        :: "r"(smem_dst), "l"(gsrc), "r"(bytes), "r"(mbar) : "memory");
}

__device__ __forceinline__ void bulk_s2g(void* gdst, uint32_t smem_src, uint32_t bytes) {
    asm volatile(
        "cp.async.bulk.global.shared::cta.bulk_group [%0], [%1], %2;"
        :: "l"(gdst), "r"(smem_src), "r"(bytes) : "memory");
}

__device__ __forceinline__ void bulk_commit() {
    asm volatile("cp.async.bulk.commit_group;" ::: "memory");
}

template <int N>
__device__ __forceinline__ void bulk_wait() {
    asm volatile("cp.async.bulk.wait_group %0;" :: "n"(N) : "memory");
}

__global__ void __launch_bounds__(THREADS) emb_async_kernel(
        const int* __restrict__ idx,
        const char* __restrict__ pages,
        char* __restrict__ out,
        int n_rows) {
    extern __shared__ char smem[];
    const uint32_t sb = smem_u32(smem);
    const int tid = threadIdx.x;
    const int lane = tid & 31;
    const int warp = tid >> 5;

    // full[s] at sb + s*8, empty[s] at sb + 64 + s*8, data at sb + 1024
    if (tid == 0) {
        #pragma unroll
        for (int s = 0; s < STAGES; s++) {
            mbar_init(sb + s * 8, 1);
            mbar_init(sb + 64 + s * 8, 1);
        }
    }
    __syncthreads();

    const int row0 = blockIdx.x * ROWS_PER_CTA;
    const int rows = min(ROWS_PER_CTA, n_rows - row0);
    if (rows <= 0) return;
    const int iters = (rows + ROWS_PER_STAGE - 1) / ROWS_PER_STAGE;

    if (warp == 0) {
        // ── Producer: issue per-row 256B bulk gathers into the ring ──
        for (int k = 0; k < iters; k++) {
            const int s = k % STAGES;
            if (k >= STAGES) {
                // wait for storer to free this stage (wrap w needs w-th arrival)
                mbar_wait(sb + 64 + s * 8, ((k / STAGES) - 1) & 1);
            }
            const int base = row0 + k * ROWS_PER_STAGE;
            const int cnt = min(ROWS_PER_STAGE, row0 + rows - base);
            if (lane == 0) mbar_expect_tx(sb + s * 8, (uint32_t)cnt * ROW_BYTES);
            __syncwarp();   // expect_tx before any complete_tx can land
            for (int r = lane; r < cnt; r += 32) {
                int iv = __ldg(&idx[base + r]);
                iv = max(0, min(iv, N_WORDS - 1));        // defensive clamp
                bulk_g2s(sb + SMEM_BUF_OFF + s * STAGE_BYTES + r * ROW_BYTES,
                         pages + (size_t)iv * ROW_BYTES,
                         ROW_BYTES,
                         sb + s * 8);
            }
        }
    } else if (warp == 1 && lane == 0) {
        // ── Storer: one 16KB bulk store per filled stage ──
        for (int k = 0; k < iters; k++) {
            const int s = k % STAGES;
            mbar_wait(sb + s * 8, (k / STAGES) & 1);      // stage full
            const int base = row0 + k * ROWS_PER_STAGE;
            const int cnt = min(ROWS_PER_STAGE, row0 + rows - base);
            bulk_s2g(out + (size_t)base * ROW_BYTES,
                     sb + SMEM_BUF_OFF + s * STAGE_BYTES,
                     (uint32_t)cnt * ROW_BYTES);
            bulk_commit();
            if (k >= 2) {
                bulk_wait<2>();                           // store k-2 done reading smem
                mbar_arrive(sb + 64 + ((k - 2) % STAGES) * 8);
            }
        }
        bulk_wait<0>();   // all stores committed to global before CTA retires
    }
}

extern "C" void kernel_launch(void* const* d_in, const int* in_sizes, int n_in,
                              void* d_out, int out_size) {
    const int*  idx   = (const int*)d_in[0];    // [16,8192] int32
    const char* pages = (const char*)d_in[1];   // [8,125000,64] fp32 = flat rows

    const int n_rows = in_sizes[0];             // 131072 lookups
    const int blocks = (n_rows + ROWS_PER_CTA - 1) / ROWS_PER_CTA;   // 512

    cudaFuncSetAttribute(emb_async_kernel,
                         cudaFuncAttributeMaxDynamicSharedMemorySize, SMEM_TOTAL);

    emb_async_kernel<<<blocks, THREADS, SMEM_TOTAL>>>(
        idx, pages, (char*)d_out, n_rows);
}

// round 11
// speedup vs baseline: 2.9495x; 2.9495x over previous
#include <cuda_runtime.h>
#include <stdint.h>

// Embedding gather: out[j*64+k] = pages[idx[j]*64+k]
// pages [8,125000,64] contiguous; (i/P)*P + i%P == i -> flat gather at idx[j]*64.
// indices int32 (JAX default x64-disabled).
//
// 32B (256-bit) per thread: 8 threads cover one 256B row. Halves the LDG/STG
// op count vs float4 (attacks the L1tex wavefront-issue bound identified in
// R5). Table reads use ld.global.nc.L2::evict_last.v4.b64 (the only widths
// ptxas accepts for evict_last) to pin the hot ~32MB of table lines in L2
// across graph replays; output uses plain stores so replay writes are L2
// write-hits instead of a forced DRAM drain (the R3-R5 __stcs mistake).
// Persistent single-wave grid, ILP=4.

#define N_WORDS 1000000
#define ILP 4
#define THREADS 256
#define BLOCKS (148 * 8)

struct v4b64 { unsigned long long a, b, c, d; };   // 32 bytes

__device__ __forceinline__ v4b64 ldg_evict_last_32B(const void* p) {
    v4b64 v;
    asm volatile("ld.global.nc.L2::evict_last.v4.b64 {%0,%1,%2,%3}, [%4];"
                 : "=l"(v.a), "=l"(v.b), "=l"(v.c), "=l"(v.d) : "l"(p));
    return v;
}

__device__ __forceinline__ void stg_32B(void* p, const v4b64& v) {
    asm volatile("st.global.v4.b64 [%0], {%1,%2,%3,%4};"
                 :: "l"(p), "l"(v.a), "l"(v.b), "l"(v.c), "l"(v.d) : "memory");
}

__global__ void __launch_bounds__(THREADS) emb_gather_kernel(
        const int* __restrict__ idx,
        const char* __restrict__ pages,
        char* __restrict__ out,
        unsigned n_chunks) {            // 32B chunks = n_lookups * 8
    const unsigned S = BLOCKS * THREADS;           // grid stride (mult of 8)
    unsigned t0 = blockIdx.x * THREADS + threadIdx.x;
    const unsigned c = (t0 & 7u) * 32u;            // byte offset in row, invariant

    for (; t0 < n_chunks; t0 += S * ILP) {
        unsigned off[ILP];                         // byte offset into pages (<2^28)
        bool ok[ILP];

        // Phase 1: independent idx loads + offset math
        #pragma unroll
        for (int u = 0; u < ILP; u++) {
            unsigned t = t0 + u * S;
            ok[u] = (t < n_chunks);
            unsigned j = t >> 3;                   // lookup id
            int iv = ok[u] ? __ldg(&idx[j]) : 0;
            iv = max(0, min(iv, N_WORDS - 1));     // defensive clamp
            off[u] = (unsigned)iv * 256u + c;
        }

        // Phase 2: independent 32B table gathers (evict-last -> hot in L2)
        v4b64 d[ILP];
        #pragma unroll
        for (int u = 0; u < ILP; u++)
            d[u] = ldg_evict_last_32B(pages + off[u]);

        // Phase 3: plain 32B stores (L2 write-hit on warm replays)
        #pragma unroll
        for (int u = 0; u < ILP; u++)
            if (ok[u]) stg_32B(out + (size_t)(t0 + u * S) * 32u, d[u]);
    }
}

extern "C" void kernel_launch(void* const* d_in, const int* in_sizes, int n_in,
                              void* d_out, int out_size) {
    const int*  idx   = (const int*)d_in[0];    // [16,8192] int32
    const char* pages = (const char*)d_in[1];   // [8,125000,64] fp32 rows of 256B

    unsigned n_lookups = (unsigned)in_sizes[0]; // 131072
    unsigned n_chunks = n_lookups * 8u;         // 1,048,576 x 32B

    emb_gather_kernel<<<BLOCKS, THREADS>>>(
        idx, pages, (char*)d_out, n_chunks);
}

// round 14
// speedup vs baseline: 3.3953x; 1.1512x over previous
#include <cuda_runtime.h>
#include <stdint.h>

// Embedding gather via cp.async (LDGSTS) staging + bulk store.
// out[j*64..] = pages[idx[j]*64..], rows of 256B, idx int32.
//
// R2-R10 showed the register-LDG path is pinned at ~11us regardless of
// ILP/width/occupancy/cache hints: gather depth is register-limited and the
// L1tex queue serializes. cp.async.cg decouples loads from registers
// (no dst reg, unbounded depth, L1-bypass), and the contiguous output is
// drained by ONE 16KB cp.async.bulk smem->global per CTA instead of 512
// STG.128 wavefront groups.
//
// CTA: 256 threads, 64 rows (16KB smem). Each thread issues 4 x 16B
// cp.async gathers, wait_group 0 + syncthreads, then thread 0 fires the
// bulk store. Cross-CTA overlap (13+ CTAs/SM) hides all latency.

#define N_WORDS      1000000
#define ROW_BYTES    256
#define ROWS_PER_CTA 64
#define THREADS      256
#define STAGE_BYTES  (ROWS_PER_CTA * ROW_BYTES)       // 16384
#define CHUNKS       (STAGE_BYTES / 16)               // 1024 x 16B
#define CH_PER_THR   (CHUNKS / THREADS)               // 4

__device__ __forceinline__ uint32_t smem_u32(const void* p) {
    uint32_t a;
    asm("{ .reg .u64 t; cvta.to.shared.u64 t, %1; cvt.u32.u64 %0, t; }"
        : "=r"(a) : "l"(p));
    return a;
}

__device__ __forceinline__ void cpasync16(uint32_t sdst, const void* gsrc) {
    asm volatile("cp.async.cg.shared.global [%0], [%1], 16;"
                 :: "r"(sdst), "l"(gsrc) : "memory");
}

__global__ void __launch_bounds__(THREADS) emb_cpasync_kernel(
        const int* __restrict__ idx,
        const char* __restrict__ pages,
        char* __restrict__ out,
        int n_rows) {
    __shared__ __align__(128) char buf[STAGE_BYTES];
    const uint32_t sb = smem_u32(buf);
    const int tid = threadIdx.x;

    const int row0 = blockIdx.x * ROWS_PER_CTA;
    if (row0 >= n_rows) return;
    const int cnt = min(ROWS_PER_CTA, n_rows - row0);   // rows this CTA

    // Phase 1: issue all 16B async gathers (4 per thread, no dst registers).
    // chunk = tid + k*THREADS ; row = chunk/16 ; c = chunk%16.
    #pragma unroll
    for (int k = 0; k < CH_PER_THR; k++) {
        int chunk = tid + k * THREADS;
        int r = chunk >> 4;
        int c = chunk & 15;
        if (r < cnt) {
            int iv = __ldg(&idx[row0 + r]);
            iv = max(0, min(iv, N_WORDS - 1));          // defensive clamp
            cpasync16(sb + chunk * 16,
                      pages + (size_t)iv * ROW_BYTES + c * 16);
        }
    }
    asm volatile("cp.async.commit_group;" ::: "memory");
    asm volatile("cp.async.wait_group 0;" ::: "memory");
    __syncthreads();

    // Phase 2: single bulk store of the whole stage (contiguous output).
    if (tid == 0) {
        asm volatile("fence.proxy.async.shared::cta;" ::: "memory");
        asm volatile(
            "cp.async.bulk.global.shared::cta.bulk_group [%0], [%1], %2;"
            :: "l"(out + (size_t)row0 * ROW_BYTES), "r"(sb),
               "r"((uint32_t)(cnt * ROW_BYTES)) : "memory");
        asm volatile("cp.async.bulk.commit_group;" ::: "memory");
        asm volatile("cp.async.bulk.wait_group 0;" ::: "memory");
    }
}

extern "C" void kernel_launch(void* const* d_in, const int* in_sizes, int n_in,
                              void* d_out, int out_size) {
    const int*  idx   = (const int*)d_in[0];    // [16,8192] int32
    const char* pages = (const char*)d_in[1];   // [8,125000,64] fp32 rows, 256B

    const int n_rows = in_sizes[0];             // 131072
    const int blocks = (n_rows + ROWS_PER_CTA - 1) / ROWS_PER_CTA;   // 2048

    emb_cpasync_kernel<<<blocks, THREADS>>>(idx, pages, (char*)d_out, n_rows);
}